// round 2
// baseline (speedup 1.0000x reference)
#include <cuda_runtime.h>
#include <math.h>

#define A_N 1000
#define N_N 2000
#define Z_N 2000
#define D_N 8

// ---------------- device scratch (no cudaMalloc allowed) ----------------
__device__ float g_T1[N_N * Z_N];        // K @ B
__device__ float g_T2[N_N * Z_N];        // K @ K @ B
__device__ float g_gX[N_N * Z_N];        // gamma_X
__device__ float g_E1c[A_N * N_N];
__device__ float g_E1s[A_N * N_N];
__device__ float g_E2c[A_N * N_N];
__device__ float g_E2s[A_N * N_N];
__device__ float g_den[4 * A_N * Z_N];   // planes: inv|p|^2, inv|q|^2, r_re, r_im
__device__ float g_acc;

__global__ void zero_acc_kernel() { g_acc = 0.f; }

// ---------------- phase features: cos/sin of alpha @ N^T and alpha @ X^T ----------------
__global__ void trig_kernel(const float* __restrict__ alpha,
                            const float* __restrict__ Nmat,
                            const float* __restrict__ Xmat) {
  int idx = blockIdx.x * blockDim.x + threadIdx.x;
  if (idx >= A_N * N_N) return;
  int a = idx / N_N;
  int j = idx - a * N_N;
  float ph1 = 0.f, ph2 = 0.f;
#pragma unroll
  for (int d = 0; d < D_N; d++) {
    float al = alpha[a * D_N + d];
    ph1 = fmaf(al, Nmat[j * D_N + d], ph1);
    ph2 = fmaf(al, Xmat[j * D_N + d], ph2);
  }
  float s1, c1, s2, c2;
  sincosf(ph1, &s1, &c1);
  sincosf(ph2, &s2, &c2);
  g_E1c[idx] = c1;
  g_E1s[idx] = s1;
  g_E2c[idx] = c2;
  g_E2s[idx] = s2;
}

// ---------------- fp32 SGEMM 2000x2000x2000 (Neumann terms) ----------------
__global__ __launch_bounds__(256) void sgemm2000(const float* __restrict__ A,
                                                 const float* __restrict__ B,
                                                 float* __restrict__ C) {
  const int M = N_N, N = Z_N, K = N_N;
  __shared__ float As[8][128];
  __shared__ float Bs[8][128];
  int tid = threadIdx.x;
  int brow = blockIdx.y * 128;
  int bcol = blockIdx.x * 128;
  int trow = (tid / 16) * 8;
  int tcol = (tid % 16) * 8;
  int arow = tid >> 1;
  int acol = (tid & 1) * 4;
  int browl = tid >> 5;
  int bcoll = (tid & 31) * 4;
  float acc[8][8];
#pragma unroll
  for (int i = 0; i < 8; i++)
#pragma unroll
    for (int j = 0; j < 8; j++) acc[i][j] = 0.f;

  const float4 zf4 = make_float4(0.f, 0.f, 0.f, 0.f);
  for (int k0 = 0; k0 < K; k0 += 8) {
    int gr = brow + arow;
    float4 av = (gr < M) ? *reinterpret_cast<const float4*>(&A[gr * K + k0 + acol]) : zf4;
    As[acol + 0][arow] = av.x;
    As[acol + 1][arow] = av.y;
    As[acol + 2][arow] = av.z;
    As[acol + 3][arow] = av.w;
    int gc = bcol + bcoll;
    float4 bv = (gc < N) ? *reinterpret_cast<const float4*>(&B[(k0 + browl) * N + gc]) : zf4;
    *reinterpret_cast<float4*>(&Bs[browl][bcoll]) = bv;
    __syncthreads();
#pragma unroll
    for (int kk = 0; kk < 8; kk++) {
      float ar[8], br[8];
#pragma unroll
      for (int i = 0; i < 8; i++) ar[i] = As[kk][trow + i];
#pragma unroll
      for (int j = 0; j < 8; j++) br[j] = Bs[kk][tcol + j];
#pragma unroll
      for (int i = 0; i < 8; i++)
#pragma unroll
        for (int j = 0; j < 8; j++) acc[i][j] = fmaf(ar[i], br[j], acc[i][j]);
    }
    __syncthreads();
  }
#pragma unroll
  for (int i = 0; i < 8; i++) {
    int r = brow + trow + i;
    if (r >= M) continue;
#pragma unroll
    for (int j = 0; j < 8; j++) {
      int c = bcol + tcol + j;
      if (c < N) C[r * N + c] = acc[i][j];
    }
  }
}

// gamma_X = (B - T1/c + T2/c^2)/c,  c = n * exp(log_lambda)
__global__ void combine_gamma_kernel(const float* __restrict__ B,
                                     const float* __restrict__ loglam) {
  int i = blockIdx.x * blockDim.x + threadIdx.x;
  if (i >= N_N * Z_N) return;
  float c = (float)N_N * expf(loglam[0]);
  float ic = 1.f / c;
  g_gX[i] = (B[i] - (g_T1[i] - g_T2[i] * ic) * ic) * ic;
}

#define LD4(dst, src)                                     \
  {                                                       \
    float4 _t = *reinterpret_cast<const float4*>(src);    \
    (dst)[0] = _t.x; (dst)[1] = _t.y;                     \
    (dst)[2] = _t.z; (dst)[3] = _t.w;                     \
  }

// ---------------- denominators: p = E1 @ gamma_N, q = E2 @ gamma_X ----------------
__global__ __launch_bounds__(256) void denom_kernel(const float* __restrict__ gammaN) {
  __shared__ float sE1c[16][64];
  __shared__ float sE1s[16][64];
  __shared__ float sE2c[16][64];
  __shared__ float sE2s[16][64];
  __shared__ float sGn[16][64];
  __shared__ float sGx[16][64];
  int tid = threadIdx.x;
  int ablk = blockIdx.y * 64;
  int zblk = blockIdx.x * 64;
  int ta = (tid / 16) * 4;
  int tz = (tid % 16) * 4;
  int e_ar = tid >> 2;
  int e_kc = (tid & 3) * 4;
  int g_kr = tid >> 4;
  int g_zc = (tid & 15) * 4;
  int ga = ablk + e_ar;
  bool a_ok = (ga < A_N);
  int gz = zblk + g_zc;
  bool z_ok = (gz < Z_N);
  const float4 zf4 = make_float4(0.f, 0.f, 0.f, 0.f);

  float pr[4][4], pim[4][4], qr[4][4], qim[4][4];
#pragma unroll
  for (int i = 0; i < 4; i++)
#pragma unroll
    for (int j = 0; j < 4; j++) { pr[i][j] = 0.f; pim[i][j] = 0.f; qr[i][j] = 0.f; qim[i][j] = 0.f; }

  for (int k0 = 0; k0 < N_N; k0 += 16) {
    int eoff = ga * N_N + k0 + e_kc;
    float4 t;
    t = a_ok ? *reinterpret_cast<const float4*>(&g_E1c[eoff]) : zf4;
    sE1c[e_kc + 0][e_ar] = t.x; sE1c[e_kc + 1][e_ar] = t.y; sE1c[e_kc + 2][e_ar] = t.z; sE1c[e_kc + 3][e_ar] = t.w;
    t = a_ok ? *reinterpret_cast<const float4*>(&g_E1s[eoff]) : zf4;
    sE1s[e_kc + 0][e_ar] = t.x; sE1s[e_kc + 1][e_ar] = t.y; sE1s[e_kc + 2][e_ar] = t.z; sE1s[e_kc + 3][e_ar] = t.w;
    t = a_ok ? *reinterpret_cast<const float4*>(&g_E2c[eoff]) : zf4;
    sE2c[e_kc + 0][e_ar] = t.x; sE2c[e_kc + 1][e_ar] = t.y; sE2c[e_kc + 2][e_ar] = t.z; sE2c[e_kc + 3][e_ar] = t.w;
    t = a_ok ? *reinterpret_cast<const float4*>(&g_E2s[eoff]) : zf4;
    sE2s[e_kc + 0][e_ar] = t.x; sE2s[e_kc + 1][e_ar] = t.y; sE2s[e_kc + 2][e_ar] = t.z; sE2s[e_kc + 3][e_ar] = t.w;

    int goff = (k0 + g_kr) * Z_N + gz;
    float4 gn = z_ok ? *reinterpret_cast<const float4*>(&gammaN[goff]) : zf4;
    *reinterpret_cast<float4*>(&sGn[g_kr][g_zc]) = gn;
    float4 gx = z_ok ? *reinterpret_cast<const float4*>(&g_gX[goff]) : zf4;
    *reinterpret_cast<float4*>(&sGx[g_kr][g_zc]) = gx;
    __syncthreads();

#pragma unroll
    for (int kk = 0; kk < 16; kk++) {
      float e1c[4], e1s[4], e2c[4], e2s[4], gn4[4], gx4[4];
      LD4(e1c, &sE1c[kk][ta]);
      LD4(e1s, &sE1s[kk][ta]);
      LD4(e2c, &sE2c[kk][ta]);
      LD4(e2s, &sE2s[kk][ta]);
      LD4(gn4, &sGn[kk][tz]);
      LD4(gx4, &sGx[kk][tz]);
#pragma unroll
      for (int i = 0; i < 4; i++)
#pragma unroll
        for (int j = 0; j < 4; j++) {
          pr[i][j]  = fmaf(e1c[i], gn4[j], pr[i][j]);
          pim[i][j] = fmaf(e1s[i], gn4[j], pim[i][j]);
          qr[i][j]  = fmaf(e2c[i], gx4[j], qr[i][j]);
          qim[i][j] = fmaf(e2s[i], gx4[j], qim[i][j]);
        }
    }
    __syncthreads();
  }

  const int PL = A_N * Z_N;
#pragma unroll
  for (int i = 0; i < 4; i++) {
    int a = ablk + ta + i;
    if (a >= A_N) continue;
#pragma unroll
    for (int j = 0; j < 4; j++) {
      int z = zblk + tz + j;
      if (z >= Z_N) continue;
      float prx = pr[i][j], pix = pim[i][j], qrx = qr[i][j], qix = qim[i][j];
      float ipp = 1.f / fmaf(prx, prx, pix * pix);
      float iqq = 1.f / fmaf(qrx, qrx, qix * qix);
      float sre = fmaf(prx, qrx, pix * qix);
      float sim = fmaf(pix, qrx, -prx * qix);
      float f = ipp * iqq;
      int o = a * Z_N + z;
      g_den[0 * PL + o] = ipp;
      g_den[1 * PL + o] = iqq;
      g_den[2 * PL + o] = sre * f;
      g_den[3 * PL + o] = -sim * f;
    }
  }
}

// ---------------- main loss: loop d, GEMM u_d, v_d, fuse epilogue ----------------
__global__ __launch_bounds__(256) void loss_kernel(const float* __restrict__ gammaMN,
                                                   const float* __restrict__ Mmat,
                                                   const float* __restrict__ Xmat) {
  __shared__ float sE1c[16][64];
  __shared__ float sE1s[16][64];
  __shared__ float sE2c[16][64];
  __shared__ float sE2s[16][64];
  __shared__ float sW1[16][64];
  __shared__ float sW2[16][64];
  __shared__ float red[256];
  int tid = threadIdx.x;
  int ablk = blockIdx.y * 64;
  int zblk = blockIdx.x * 64;
  int ta = (tid / 16) * 4;
  int tz = (tid % 16) * 4;
  int e_ar = tid >> 2;
  int e_kc = (tid & 3) * 4;
  int g_kr = tid >> 4;
  int g_zc = (tid & 15) * 4;
  int ga = ablk + e_ar;
  bool a_ok = (ga < A_N);
  int gz = zblk + g_zc;
  bool z_ok = (gz < Z_N);
  const float4 zf4 = make_float4(0.f, 0.f, 0.f, 0.f);
  const int PL = A_N * Z_N;
  float lsum = 0.f;

  for (int d = 0; d < D_N; d++) {
    float ur[4][4], ui[4][4], vr[4][4], vi[4][4];
#pragma unroll
    for (int i = 0; i < 4; i++)
#pragma unroll
      for (int j = 0; j < 4; j++) { ur[i][j] = 0.f; ui[i][j] = 0.f; vr[i][j] = 0.f; vi[i][j] = 0.f; }

    for (int k0 = 0; k0 < N_N; k0 += 16) {
      int eoff = ga * N_N + k0 + e_kc;
      float4 t;
      t = a_ok ? *reinterpret_cast<const float4*>(&g_E1c[eoff]) : zf4;
      sE1c[e_kc + 0][e_ar] = t.x; sE1c[e_kc + 1][e_ar] = t.y; sE1c[e_kc + 2][e_ar] = t.z; sE1c[e_kc + 3][e_ar] = t.w;
      t = a_ok ? *reinterpret_cast<const float4*>(&g_E1s[eoff]) : zf4;
      sE1s[e_kc + 0][e_ar] = t.x; sE1s[e_kc + 1][e_ar] = t.y; sE1s[e_kc + 2][e_ar] = t.z; sE1s[e_kc + 3][e_ar] = t.w;
      t = a_ok ? *reinterpret_cast<const float4*>(&g_E2c[eoff]) : zf4;
      sE2c[e_kc + 0][e_ar] = t.x; sE2c[e_kc + 1][e_ar] = t.y; sE2c[e_kc + 2][e_ar] = t.z; sE2c[e_kc + 3][e_ar] = t.w;
      t = a_ok ? *reinterpret_cast<const float4*>(&g_E2s[eoff]) : zf4;
      sE2s[e_kc + 0][e_ar] = t.x; sE2s[e_kc + 1][e_ar] = t.y; sE2s[e_kc + 2][e_ar] = t.z; sE2s[e_kc + 3][e_ar] = t.w;

      int jg = k0 + g_kr;
      float m_d = Mmat[jg * D_N + d];
      float x_d = Xmat[jg * D_N + d];
      int goff = jg * Z_N + gz;
      float4 gmn = z_ok ? *reinterpret_cast<const float4*>(&gammaMN[goff]) : zf4;
      float4 gxx = z_ok ? *reinterpret_cast<const float4*>(&g_gX[goff]) : zf4;
      float4 w1 = make_float4(gmn.x * m_d, gmn.y * m_d, gmn.z * m_d, gmn.w * m_d);
      float4 w2 = make_float4(gxx.x * x_d, gxx.y * x_d, gxx.z * x_d, gxx.w * x_d);
      *reinterpret_cast<float4*>(&sW1[g_kr][g_zc]) = w1;
      *reinterpret_cast<float4*>(&sW2[g_kr][g_zc]) = w2;
      __syncthreads();

#pragma unroll
      for (int kk = 0; kk < 16; kk++) {
        float e1c[4], e1s[4], e2c[4], e2s[4], wa[4], wb[4];
        LD4(e1c, &sE1c[kk][ta]);
        LD4(e1s, &sE1s[kk][ta]);
        LD4(e2c, &sE2c[kk][ta]);
        LD4(e2s, &sE2s[kk][ta]);
        LD4(wa, &sW1[kk][tz]);
        LD4(wb, &sW2[kk][tz]);
#pragma unroll
        for (int i = 0; i < 4; i++)
#pragma unroll
          for (int j = 0; j < 4; j++) {
            ur[i][j] = fmaf(e1c[i], wa[j], ur[i][j]);
            ui[i][j] = fmaf(e1s[i], wa[j], ui[i][j]);
            vr[i][j] = fmaf(e2c[i], wb[j], vr[i][j]);
            vi[i][j] = fmaf(e2s[i], wb[j], vi[i][j]);
          }
      }
      __syncthreads();
    }

    // per-d epilogue: |u/p - v/q|^2 contribution via precomputed denominator planes
#pragma unroll
    for (int i = 0; i < 4; i++) {
      int a = ablk + ta + i;
      if (a >= A_N) continue;
#pragma unroll
      for (int j = 0; j < 4; j++) {
        int z = zblk + tz + j;
        if (z >= Z_N) continue;
        int o = a * Z_N + z;
        float ipp = g_den[0 * PL + o];
        float iqq = g_den[1 * PL + o];
        float rre = g_den[2 * PL + o];
        float rim = g_den[3 * PL + o];
        float a0 = ur[i][j], b0 = ui[i][j], c0 = vr[i][j], d0 = vi[i][j];
        float uu = fmaf(a0, a0, b0 * b0);
        float vv = fmaf(c0, c0, d0 * d0);
        float xr = fmaf(a0, c0, b0 * d0);
        float xi = fmaf(b0, c0, -a0 * d0);
        lsum += fmaf(uu, ipp, vv * iqq) - 2.f * fmaf(xr, rre, -xi * rim);
      }
    }
  }

  red[tid] = lsum;
  __syncthreads();
  for (int s = 128; s > 0; s >>= 1) {
    if (tid < s) red[tid] += red[tid + s];
    __syncthreads();
  }
  if (tid == 0) atomicAdd(&g_acc, red[0]);
}

__global__ void finalize_kernel(float* out) {
  out[0] = g_acc * (1.f / (float)(A_N * Z_N));
}

// ---------------- launch ----------------
extern "C" void kernel_launch(void* const* d_in, const int* in_sizes, int n_in,
                              void* d_out, int out_size) {
  const float* Mmat  = (const float*)d_in[0];
  const float* Nmat  = (const float*)d_in[1];
  const float* Xmat  = (const float*)d_in[2];
  const float* llam  = (const float*)d_in[3];
  const float* Kz    = (const float*)d_in[4];
  const float* Bz    = (const float*)d_in[5];
  const float* gMN   = (const float*)d_in[6];
  const float* gN    = (const float*)d_in[7];
  const float* alpha = (const float*)d_in[8];
  float* out = (float*)d_out;

  float *pT1, *pT2;
  cudaGetSymbolAddress((void**)&pT1, g_T1);
  cudaGetSymbolAddress((void**)&pT2, g_T2);

  zero_acc_kernel<<<1, 1>>>();
  trig_kernel<<<(A_N * N_N + 255) / 256, 256>>>(alpha, Nmat, Xmat);

  dim3 gg((Z_N + 127) / 128, (N_N + 127) / 128);
  sgemm2000<<<gg, 256>>>(Kz, Bz, pT1);
  sgemm2000<<<gg, 256>>>(Kz, pT1, pT2);
  combine_gamma_kernel<<<(N_N * Z_N + 255) / 256, 256>>>(Bz, llam);

  dim3 gd((Z_N + 63) / 64, (A_N + 63) / 64);
  denom_kernel<<<gd, 256>>>(gN);
  loss_kernel<<<gd, 256>>>(gMN, Mmat, Xmat);
  finalize_kernel<<<1, 1>>>(out);
}